// round 1
// baseline (speedup 1.0000x reference)
#include <cuda_runtime.h>
#include <math.h>

#define NN 50000
#define NE 800000
#define IND 128
#define OUTD 64
#define THALF 64
#define TABN 4096

// sqrt(1/128)
#define TSCALE 0.08838834764831845f

// ---------------- scratch (static __device__, no allocations) ----------------
__device__ float g_p1[IND];
__device__ float g_p2[IND];
__device__ float g_q[2 * THALF];
__device__ float g_tab[TABN + 1];
__device__ float g_WvT[IND * OUTD];          // [k][c] layout
__device__ float g_s1[NN];
__device__ float g_s2[NN];
__device__ float g_hv[NN * OUTD];
__device__ float g_e[NE];
__device__ float g_esort[NE];
__device__ int   g_ssort[NE];
__device__ int   g_cnt[NN];
__device__ int   g_off[NN + 1];
__device__ int   g_cur[NN];

// ---------------- tiny prep: p1 = W^T a1, p2 = W^T a2, q = Wt^T a3 ----------
__global__ void k_prep(const float* __restrict__ W, const float* __restrict__ Wt,
                       const float* __restrict__ a) {
    int t = threadIdx.x;  // 384 threads
    if (t < 128) {
        float s = 0.f;
        #pragma unroll 8
        for (int i = 0; i < 64; i++) s += W[i * 128 + t] * a[i];
        g_p1[t] = s;
    } else if (t < 256) {
        int k = t - 128;
        float s = 0.f;
        #pragma unroll 8
        for (int i = 0; i < 64; i++) s += W[i * 128 + k] * a[64 + i];
        g_p2[k] = s;
    } else {
        int k = t - 256;
        float s = 0.f;
        #pragma unroll 8
        for (int i = 0; i < 64; i++) s += Wt[i * 128 + k] * a[128 + i];
        g_q[k] = s;
    }
}

// ---------------- transpose Wv -> WvT[k*64+c] --------------------------------
__global__ void k_transpose(const float* __restrict__ Wv) {
    int i = blockIdx.x * 256 + threadIdx.x;
    if (i < IND * OUTD) {
        int c = i & 63;
        int k = i >> 6;
        g_WvT[i] = Wv[c * 128 + k];
    }
}

// ---------------- temporal-term lookup table over t in [0,1] -----------------
__global__ void k_table(const float* __restrict__ omega) {
    int i = blockIdx.x * 256 + threadIdx.x;
    if (i <= TABN) {
        float t = (float)i / (float)TABN;
        float s = 0.f;
        for (int j = 0; j < THALF; j++) {
            float sn, cs;
            sincosf(t * omega[j], &sn, &cs);
            s += sn * g_q[2 * j] + cs * g_q[2 * j + 1];
        }
        g_tab[i] = s * TSCALE;
    }
}

// ---------------- per-node scalars s1, s2 (warp per node) + zero counts ------
__global__ void k_node(const float* __restrict__ x) {
    int g = blockIdx.x * 256 + threadIdx.x;
    if (g < NN) g_cnt[g] = 0;

    int n = blockIdx.x * 8 + (threadIdx.x >> 5);
    int lane = threadIdx.x & 31;
    if (n >= NN) return;
    const float* xr = x + (size_t)n * IND;
    float d1 = 0.f, d2 = 0.f;
    #pragma unroll
    for (int j = 0; j < 4; j++) {
        float xv = xr[lane + 32 * j];
        d1 += xv * g_p1[lane + 32 * j];
        d2 += xv * g_p2[lane + 32 * j];
    }
    #pragma unroll
    for (int o = 16; o; o >>= 1) {
        d1 += __shfl_xor_sync(0xffffffffu, d1, o);
        d2 += __shfl_xor_sync(0xffffffffu, d2, o);
    }
    if (lane == 0) { g_s1[n] = d1; g_s2[n] = d2; }
}

// ---------------- hv = X @ Wv^T  (tiled fp32 GEMM, 64x64 tile, 4x8/thread) ---
__global__ void __launch_bounds__(128) k_hv(const float* __restrict__ x) {
    __shared__ float sX[64][65];   // [row][k-in-tile], pad -> conflict-free
    __shared__ float sB[64][64];   // [k-in-tile][col], float4-aligned

    int n0 = blockIdx.x * 64;
    int tid = threadIdx.x;           // 128 threads
    int tr = (tid >> 3) * 4;         // node sub-row base (0..60)
    int tc = (tid & 7) * 8;          // col base (0..56)

    float acc[4][8];
    #pragma unroll
    for (int r = 0; r < 4; r++)
        #pragma unroll
        for (int c = 0; c < 8; c++) acc[r][c] = 0.f;

    for (int kt = 0; kt < 2; kt++) {
        // load X tile: 64 rows x 64 k, float4 reads (coalesced), scalar stores
        for (int i = tid; i < 1024; i += 128) {
            int r  = i >> 4;         // 16 float4 per row
            int c4 = i & 15;
            int n = n0 + r;
            float4 v = (n < NN)
                ? *(const float4*)(x + (size_t)n * 128 + kt * 64 + c4 * 4)
                : make_float4(0.f, 0.f, 0.f, 0.f);
            sX[r][c4 * 4 + 0] = v.x;
            sX[r][c4 * 4 + 1] = v.y;
            sX[r][c4 * 4 + 2] = v.z;
            sX[r][c4 * 4 + 3] = v.w;
        }
        // load B tile straight from pre-transposed WvT (fully coalesced/aligned)
        for (int i = tid; i < 1024; i += 128) {
            ((float4*)&sB[0][0])[i] = ((const float4*)(g_WvT + kt * 64 * 64))[i];
        }
        __syncthreads();

        #pragma unroll 4
        for (int k = 0; k < 64; k++) {
            float xr4[4];
            #pragma unroll
            for (int r = 0; r < 4; r++) xr4[r] = sX[tr + r][k];
            float4 b0 = *(float4*)&sB[k][tc];
            float4 b1 = *(float4*)&sB[k][tc + 4];
            float bb[8] = {b0.x, b0.y, b0.z, b0.w, b1.x, b1.y, b1.z, b1.w};
            #pragma unroll
            for (int r = 0; r < 4; r++)
                #pragma unroll
                for (int c = 0; c < 8; c++)
                    acc[r][c] += xr4[r] * bb[c];
        }
        __syncthreads();
    }

    #pragma unroll
    for (int r = 0; r < 4; r++) {
        int n = n0 + tr + r;
        if (n < NN) {
            float4 o0 = make_float4(acc[r][0], acc[r][1], acc[r][2], acc[r][3]);
            float4 o1 = make_float4(acc[r][4], acc[r][5], acc[r][6], acc[r][7]);
            *(float4*)(g_hv + (size_t)n * 64 + tc)     = o0;
            *(float4*)(g_hv + (size_t)n * 64 + tc + 4) = o1;
        }
    }
}

// ---------------- per-edge logits + degree histogram --------------------------
__global__ void k_edge(const float* __restrict__ td, const int* __restrict__ src,
                       const int* __restrict__ dst, const float* __restrict__ omega) {
    int i = blockIdx.x * 256 + threadIdx.x;
    if (i >= NE) return;
    float t = td[i];
    int s = src[i], d = dst[i];
    float tt;
    if (t >= 0.f && t <= 1.f) {
        float u = t * (float)TABN;
        int i0 = (int)u;
        if (i0 >= TABN) i0 = TABN - 1;
        float f = u - (float)i0;
        float v0 = g_tab[i0], v1 = g_tab[i0 + 1];
        tt = v0 + f * (v1 - v0);
    } else {
        // out-of-range fallback: exact evaluation
        float acc = 0.f;
        for (int j = 0; j < THALF; j++) {
            float sn, cs;
            sincosf(t * omega[j], &sn, &cs);
            acc += sn * g_q[2 * j] + cs * g_q[2 * j + 1];
        }
        tt = acc * TSCALE;
    }
    float e = g_s1[s] + g_s2[d] + tt;
    e = (e > 0.f) ? e : 0.2f * e;   // LeakyReLU(0.2)
    g_e[i] = e;
    atomicAdd(&g_cnt[d], 1);
}

// ---------------- exclusive scan of counts -> offsets (single block) ---------
__global__ void k_scan() {
    __shared__ int ssum[1024];
    const int T = 1024;
    const int C = (NN + T - 1) / T;   // 49
    int tid = threadIdx.x;
    int base = tid * C;

    int s = 0;
    for (int j = 0; j < C; j++) {
        int idx = base + j;
        if (idx < NN) s += g_cnt[idx];
    }
    ssum[tid] = s;
    __syncthreads();
    // inclusive Hillis-Steele
    for (int off = 1; off < T; off <<= 1) {
        int v = (tid >= off) ? ssum[tid - off] : 0;
        __syncthreads();
        ssum[tid] += v;
        __syncthreads();
    }
    int run = (tid > 0) ? ssum[tid - 1] : 0;
    for (int j = 0; j < C; j++) {
        int idx = base + j;
        if (idx < NN) {
            g_off[idx] = run;
            g_cur[idx] = run;
            run += g_cnt[idx];
        }
    }
    if (tid == T - 1) g_off[NN] = ssum[T - 1];
}

// ---------------- scatter edges into CSR order -------------------------------
__global__ void k_scatter(const int* __restrict__ src, const int* __restrict__ dst) {
    int i = blockIdx.x * 256 + threadIdx.x;
    if (i >= NE) return;
    int d = dst[i];
    int pos = atomicAdd(&g_cur[d], 1);
    g_esort[pos] = g_e[i];
    g_ssort[pos] = src[i];
}

// ---------------- warp-per-node softmax + weighted aggregation ---------------
__global__ void k_agg(float* __restrict__ out) {
    int n = blockIdx.x * 8 + (threadIdx.x >> 5);
    int lane = threadIdx.x & 31;
    if (n >= NN) return;
    int start = g_off[n], end = g_off[n + 1];

    // pass A: max
    float m = -3.402823e38f;
    for (int k = start + lane; k < end; k += 32) m = fmaxf(m, g_esort[k]);
    #pragma unroll
    for (int o = 16; o; o >>= 1) m = fmaxf(m, __shfl_xor_sync(0xffffffffu, m, o));

    // pass B: sum of exp
    float ssum = 0.f;
    for (int k = start + lane; k < end; k += 32) ssum += __expf(g_esort[k] - m);
    #pragma unroll
    for (int o = 16; o; o >>= 1) ssum += __shfl_xor_sync(0xffffffffu, ssum, o);
    float inv = (end > start) ? 1.f / ssum : 0.f;

    // pass C: alpha-weighted gather-accumulate (alpha broadcast via shuffles)
    float a0 = 0.f, a1 = 0.f;
    for (int base = start; base < end; base += 32) {
        int k = base + lane;
        float ex = 0.f;
        int si = 0;
        if (k < end) {
            ex = __expf(g_esort[k] - m) * inv;
            si = g_ssort[k];
        }
        int c = end - base;
        if (c > 32) c = 32;
        for (int j = 0; j < c; j++) {
            float al = __shfl_sync(0xffffffffu, ex, j);
            int sj   = __shfl_sync(0xffffffffu, si, j);
            const float* hp = g_hv + (size_t)sj * 64;
            a0 += al * hp[lane];
            a1 += al * hp[lane + 32];
        }
    }
    out[(size_t)n * 64 + lane]      = a0;
    out[(size_t)n * 64 + 32 + lane] = a1;
}

// ---------------- launcher ---------------------------------------------------
extern "C" void kernel_launch(void* const* d_in, const int* in_sizes, int n_in,
                              void* d_out, int out_size) {
    const float* node_feats = (const float*)d_in[0];
    const float* time_diff  = (const float*)d_in[1];
    const int*   src        = (const int*)d_in[2];
    const int*   dst        = (const int*)d_in[3];
    const float* W          = (const float*)d_in[4];
    const float* Wv         = (const float*)d_in[5];
    const float* omega      = (const float*)d_in[6];
    const float* Wt         = (const float*)d_in[7];
    const float* a          = (const float*)d_in[8];
    float* out = (float*)d_out;

    k_prep<<<1, 384>>>(W, Wt, a);
    k_transpose<<<(IND * OUTD + 255) / 256, 256>>>(Wv);
    k_table<<<(TABN + 1 + 255) / 256, 256>>>(omega);
    k_node<<<(NN + 7) / 8, 256>>>(node_feats);
    k_hv<<<(NN + 63) / 64, 128>>>(node_feats);
    k_edge<<<(NE + 255) / 256, 256>>>(time_diff, src, dst, omega);
    k_scan<<<1, 1024>>>();
    k_scatter<<<(NE + 255) / 256, 256>>>(src, dst);
    k_agg<<<(NN + 7) / 8, 256>>>(out);
}

// round 3
// speedup vs baseline: 1.1133x; 1.1133x over previous
#include <cuda_runtime.h>
#include <math.h>

#define NN 50000
#define NE 800000
#define IND 128
#define OUTD 64
#define THALF 64
#define TABN 4096

// sqrt(1/128)
#define TSCALE 0.08838834764831845f

// ---------------- scratch (static __device__, no allocations) ----------------
__device__ float g_p1[IND];
__device__ float g_p2[IND];
__device__ float g_q[2 * THALF];
__device__ float g_tab[TABN + 1];
__device__ float g_WvT[IND * OUTD];          // [k][c] layout
__device__ float g_s1[NN];
__device__ float g_s2[NN];
__device__ float g_hv[NN * OUTD];
__device__ float g_esort[NE];
__device__ int   g_ssort[NE];
__device__ int   g_cnt[NN];
__device__ int   g_off[NN + 1];
__device__ int   g_cur[NN];

// ---------------- fused setup kernel -----------------------------------------
// block 0           : p1 = W^T a1, p2 = W^T a2
// block 1           : g_q = Wt^T a3 (global, for out-of-range fallback)
// blocks 2..18      : temporal lookup table (q recomputed in smem per block)
// blocks 19..50     : WvT transpose (8192 elems) + zero g_cnt
__global__ void k_setup(const float* __restrict__ W, const float* __restrict__ Wt,
                        const float* __restrict__ a, const float* __restrict__ Wv,
                        const float* __restrict__ omega) {
    int b = blockIdx.x;
    int t = threadIdx.x;

    if (b == 0) {
        if (t < 128) {
            float s = 0.f;
            #pragma unroll 8
            for (int i = 0; i < 64; i++) s += W[i * 128 + t] * a[i];
            g_p1[t] = s;
        } else {
            int k = t - 128;
            float s = 0.f;
            #pragma unroll 8
            for (int i = 0; i < 64; i++) s += W[i * 128 + k] * a[64 + i];
            g_p2[k] = s;
        }
    } else if (b == 1) {
        if (t < 128) {
            float s = 0.f;
            #pragma unroll 8
            for (int i = 0; i < 64; i++) s += Wt[i * 128 + t] * a[128 + i];
            g_q[t] = s;
        }
    } else if (b < 19) {
        __shared__ float qs[128];
        if (t < 128) {
            float s = 0.f;
            #pragma unroll 8
            for (int i = 0; i < 64; i++) s += Wt[i * 128 + t] * a[128 + i];
            qs[t] = s;
        }
        __syncthreads();
        int idx = (b - 2) * 256 + t;
        if (idx <= TABN) {
            float tt = (float)idx / (float)TABN;
            float s = 0.f;
            #pragma unroll 4
            for (int j = 0; j < THALF; j++) {
                float sn, cs;
                __sincosf(tt * omega[j], &sn, &cs);
                s += sn * qs[2 * j] + cs * qs[2 * j + 1];
            }
            g_tab[idx] = s * TSCALE;
        }
    } else {
        int j = (b - 19) * 256 + t;        // 0..8191
        // WvT transpose: [k][c] <- Wv[c][k]
        int c = j & 63;
        int k = j >> 6;
        g_WvT[j] = Wv[c * 128 + k];
        // zero counters (stride 8192)
        for (int i = j; i < NN; i += 8192) g_cnt[i] = 0;
    }
}

// ---------------- hv = X @ Wv^T  + fused s1/s2 per-node scalars --------------
__global__ void __launch_bounds__(128) k_hv(const float* __restrict__ x) {
    __shared__ float sX[64][65];   // [row][k-in-tile], pad -> conflict-free
    __shared__ float sB[64][64];   // [k-in-tile][col]

    int n0 = blockIdx.x * 64;
    int tid = threadIdx.x;           // 128 threads
    int tr = (tid >> 3) * 4;         // node sub-row base (0..60)
    int tc = (tid & 7) * 8;          // col base (0..56)

    float acc[4][8];
    #pragma unroll
    for (int r = 0; r < 4; r++)
        #pragma unroll
        for (int c = 0; c < 8; c++) acc[r][c] = 0.f;

    float s1p = 0.f, s2p = 0.f;      // threads 0..63: per-row attention scalars

    for (int kt = 0; kt < 2; kt++) {
        for (int i = tid; i < 1024; i += 128) {
            int r  = i >> 4;
            int c4 = i & 15;
            int n = n0 + r;
            float4 v = (n < NN)
                ? *(const float4*)(x + (size_t)n * 128 + kt * 64 + c4 * 4)
                : make_float4(0.f, 0.f, 0.f, 0.f);
            sX[r][c4 * 4 + 0] = v.x;
            sX[r][c4 * 4 + 1] = v.y;
            sX[r][c4 * 4 + 2] = v.z;
            sX[r][c4 * 4 + 3] = v.w;
        }
        for (int i = tid; i < 1024; i += 128) {
            ((float4*)&sB[0][0])[i] = ((const float4*)(g_WvT + kt * 64 * 64))[i];
        }
        __syncthreads();

        // fused per-node attention scalars (one row per thread, threads 0..63)
        if (tid < 64) {
            #pragma unroll 8
            for (int k = 0; k < 64; k++) {
                float xv = sX[tid][k];
                s1p = fmaf(xv, g_p1[kt * 64 + k], s1p);
                s2p = fmaf(xv, g_p2[kt * 64 + k], s2p);
            }
        }

        #pragma unroll 4
        for (int k = 0; k < 64; k++) {
            float xr4[4];
            #pragma unroll
            for (int r = 0; r < 4; r++) xr4[r] = sX[tr + r][k];
            float4 b0 = *(float4*)&sB[k][tc];
            float4 b1 = *(float4*)&sB[k][tc + 4];
            float bb[8] = {b0.x, b0.y, b0.z, b0.w, b1.x, b1.y, b1.z, b1.w};
            #pragma unroll
            for (int r = 0; r < 4; r++)
                #pragma unroll
                for (int c = 0; c < 8; c++)
                    acc[r][c] += xr4[r] * bb[c];
        }
        __syncthreads();
    }

    if (tid < 64) {
        int n = n0 + tid;
        if (n < NN) { g_s1[n] = s1p; g_s2[n] = s2p; }
    }

    #pragma unroll
    for (int r = 0; r < 4; r++) {
        int n = n0 + tr + r;
        if (n < NN) {
            float4 o0 = make_float4(acc[r][0], acc[r][1], acc[r][2], acc[r][3]);
            float4 o1 = make_float4(acc[r][4], acc[r][5], acc[r][6], acc[r][7]);
            *(float4*)(g_hv + (size_t)n * 64 + tc)     = o0;
            *(float4*)(g_hv + (size_t)n * 64 + tc + 4) = o1;
        }
    }
}

// ---------------- degree histogram (4 edges per thread, int4 load) ----------
__global__ void k_count(const int* __restrict__ dst) {
    int i = blockIdx.x * 256 + threadIdx.x;      // NE/4 = 200000 threads
    if (i * 4 >= NE) return;
    int4 d4 = ((const int4*)dst)[i];
    atomicAdd(&g_cnt[d4.x], 1);
    atomicAdd(&g_cnt[d4.y], 1);
    atomicAdd(&g_cnt[d4.z], 1);
    atomicAdd(&g_cnt[d4.w], 1);
}

// ---------------- exclusive scan of counts -> offsets (single block) ---------
__global__ void k_scan() {
    __shared__ int ssum[1024];
    const int T = 1024;
    const int C = (NN + T - 1) / T;   // 49
    int tid = threadIdx.x;
    int base = tid * C;

    int s = 0;
    for (int j = 0; j < C; j++) {
        int idx = base + j;
        if (idx < NN) s += g_cnt[idx];
    }
    ssum[tid] = s;
    __syncthreads();
    for (int off = 1; off < T; off <<= 1) {
        int v = (tid >= off) ? ssum[tid - off] : 0;
        __syncthreads();
        ssum[tid] += v;
        __syncthreads();
    }
    int run = (tid > 0) ? ssum[tid - 1] : 0;
    for (int j = 0; j < C; j++) {
        int idx = base + j;
        if (idx < NN) {
            g_off[idx] = run;
            g_cur[idx] = run;
            run += g_cnt[idx];
        }
    }
    if (tid == T - 1) g_off[NN] = ssum[T - 1];
}

// ---------------- fused logit + scatter into CSR order -----------------------
__global__ void k_scatter(const float* __restrict__ td, const int* __restrict__ src,
                          const int* __restrict__ dst, const float* __restrict__ omega) {
    int i = blockIdx.x * 256 + threadIdx.x;
    if (i >= NE) return;
    float t = td[i];
    int s = src[i], d = dst[i];
    float tt;
    if (t >= 0.f && t <= 1.f) {
        float u = t * (float)TABN;
        int i0 = (int)u;
        if (i0 >= TABN) i0 = TABN - 1;
        float f = u - (float)i0;
        float v0 = g_tab[i0], v1 = g_tab[i0 + 1];
        tt = v0 + f * (v1 - v0);
    } else {
        float acc = 0.f;
        for (int j = 0; j < THALF; j++) {
            float sn, cs;
            sincosf(t * omega[j], &sn, &cs);
            acc += sn * g_q[2 * j] + cs * g_q[2 * j + 1];
        }
        tt = acc * TSCALE;
    }
    float e = g_s1[s] + g_s2[d] + tt;
    e = (e > 0.f) ? e : 0.2f * e;   // LeakyReLU(0.2)
    int pos = atomicAdd(&g_cur[d], 1);
    g_esort[pos] = e;
    g_ssort[pos] = s;
}

// ---------------- warp-per-node softmax + weighted aggregation ---------------
__global__ void k_agg(float* __restrict__ out) {
    int n = blockIdx.x * 8 + (threadIdx.x >> 5);
    int lane = threadIdx.x & 31;
    if (n >= NN) return;
    int start = g_off[n], end = g_off[n + 1];

    // pass A: max (lane-strided, coalesced)
    float m = -3.402823e38f;
    for (int k = start + lane; k < end; k += 32) m = fmaxf(m, g_esort[k]);
    #pragma unroll
    for (int o = 16; o; o >>= 1) m = fmaxf(m, __shfl_xor_sync(0xffffffffu, m, o));

    // pass B: sum of exp
    float ssum = 0.f;
    for (int k = start + lane; k < end; k += 32) ssum += __expf(g_esort[k] - m);
    #pragma unroll
    for (int o = 16; o; o >>= 1) ssum += __shfl_xor_sync(0xffffffffu, ssum, o);
    float inv = (end > start) ? 1.f / ssum : 0.f;

    // pass C: uniform broadcast loads of (e, src); gather hv rows; normalize at end
    float a0 = 0.f, a1 = 0.f;
    #pragma unroll 2
    for (int k = start; k < end; k++) {
        float al = __expf(g_esort[k] - m);
        int sj   = g_ssort[k];
        const float* hp = g_hv + (size_t)sj * 64;
        a0 = fmaf(al, hp[lane],      a0);
        a1 = fmaf(al, hp[lane + 32], a1);
    }
    out[(size_t)n * 64 + lane]      = a0 * inv;
    out[(size_t)n * 64 + 32 + lane] = a1 * inv;
}

// ---------------- launcher ---------------------------------------------------
extern "C" void kernel_launch(void* const* d_in, const int* in_sizes, int n_in,
                              void* d_out, int out_size) {
    const float* node_feats = (const float*)d_in[0];
    const float* time_diff  = (const float*)d_in[1];
    const int*   src        = (const int*)d_in[2];
    const int*   dst        = (const int*)d_in[3];
    const float* W          = (const float*)d_in[4];
    const float* Wv         = (const float*)d_in[5];
    const float* omega      = (const float*)d_in[6];
    const float* Wt         = (const float*)d_in[7];
    const float* a          = (const float*)d_in[8];
    float* out = (float*)d_out;

    k_setup<<<51, 256>>>(W, Wt, a, Wv, omega);
    k_hv<<<(NN + 63) / 64, 128>>>(node_feats);
    k_count<<<(NE / 4 + 255) / 256, 256>>>(dst);
    k_scan<<<1, 1024>>>();
    k_scatter<<<(NE + 255) / 256, 256>>>(time_diff, src, dst, omega);
    k_agg<<<(NN + 7) / 8, 256>>>(out);
}

// round 4
// speedup vs baseline: 1.8549x; 1.6661x over previous
#include <cuda_runtime.h>
#include <math.h>

#define NN 50000
#define NE 800000
#define IND 128
#define OUTD 64
#define THALF 64
#define TABN 4096
#define SCAN_BLOCKS 49   // ceil(50000 / 1024)

// sqrt(1/128)
#define TSCALE 0.08838834764831845f

// ---------------- scratch (static __device__, no allocations) ----------------
__device__ float g_p1[IND];
__device__ float g_p2[IND];
__device__ float g_q[2 * THALF];
__device__ float g_tab[TABN + 1];
__device__ float g_WvT[IND * OUTD];          // [k][c] layout
__device__ float g_s1[NN];
__device__ float g_s2[NN];
__device__ float g_hv[NN * OUTD];
__device__ float g_esort[NE];
__device__ int   g_ssort[NE];
__device__ int   g_cnt[NN];
__device__ int   g_off[NN + 1];
__device__ int   g_cur[NN];
__device__ int   g_bsum[SCAN_BLOCKS];
__device__ int   g_bpre[SCAN_BLOCKS];

// ---------------- fused setup kernel -----------------------------------------
__global__ void k_setup(const float* __restrict__ W, const float* __restrict__ Wt,
                        const float* __restrict__ a, const float* __restrict__ Wv,
                        const float* __restrict__ omega) {
    int b = blockIdx.x;
    int t = threadIdx.x;

    if (b == 0) {
        if (t < 128) {
            float s = 0.f;
            #pragma unroll 8
            for (int i = 0; i < 64; i++) s += W[i * 128 + t] * a[i];
            g_p1[t] = s;
        } else {
            int k = t - 128;
            float s = 0.f;
            #pragma unroll 8
            for (int i = 0; i < 64; i++) s += W[i * 128 + k] * a[64 + i];
            g_p2[k] = s;
        }
    } else if (b == 1) {
        if (t < 128) {
            float s = 0.f;
            #pragma unroll 8
            for (int i = 0; i < 64; i++) s += Wt[i * 128 + t] * a[128 + i];
            g_q[t] = s;
        }
    } else if (b < 19) {
        __shared__ float qs[128];
        if (t < 128) {
            float s = 0.f;
            #pragma unroll 8
            for (int i = 0; i < 64; i++) s += Wt[i * 128 + t] * a[128 + i];
            qs[t] = s;
        }
        __syncthreads();
        int idx = (b - 2) * 256 + t;
        if (idx <= TABN) {
            float tt = (float)idx / (float)TABN;
            float s = 0.f;
            #pragma unroll 4
            for (int j = 0; j < THALF; j++) {
                float sn, cs;
                __sincosf(tt * omega[j], &sn, &cs);
                s += sn * qs[2 * j] + cs * qs[2 * j + 1];
            }
            g_tab[idx] = s * TSCALE;
        }
    } else {
        int j = (b - 19) * 256 + t;        // 0..8191
        int c = j & 63;
        int k = j >> 6;
        g_WvT[j] = Wv[c * 128 + k];
        for (int i = j; i < NN; i += 8192) g_cnt[i] = 0;
    }
}

// ---------------- hv = X @ Wv^T  + fused s1/s2 per-node scalars --------------
__global__ void __launch_bounds__(128) k_hv(const float* __restrict__ x) {
    __shared__ float sX[64][65];
    __shared__ float sB[64][64];

    int n0 = blockIdx.x * 64;
    int tid = threadIdx.x;
    int tr = (tid >> 3) * 4;
    int tc = (tid & 7) * 8;

    float acc[4][8];
    #pragma unroll
    for (int r = 0; r < 4; r++)
        #pragma unroll
        for (int c = 0; c < 8; c++) acc[r][c] = 0.f;

    float s1p = 0.f, s2p = 0.f;

    for (int kt = 0; kt < 2; kt++) {
        for (int i = tid; i < 1024; i += 128) {
            int r  = i >> 4;
            int c4 = i & 15;
            int n = n0 + r;
            float4 v = (n < NN)
                ? *(const float4*)(x + (size_t)n * 128 + kt * 64 + c4 * 4)
                : make_float4(0.f, 0.f, 0.f, 0.f);
            sX[r][c4 * 4 + 0] = v.x;
            sX[r][c4 * 4 + 1] = v.y;
            sX[r][c4 * 4 + 2] = v.z;
            sX[r][c4 * 4 + 3] = v.w;
        }
        for (int i = tid; i < 1024; i += 128) {
            ((float4*)&sB[0][0])[i] = ((const float4*)(g_WvT + kt * 64 * 64))[i];
        }
        __syncthreads();

        if (tid < 64) {
            #pragma unroll 8
            for (int k = 0; k < 64; k++) {
                float xv = sX[tid][k];
                s1p = fmaf(xv, g_p1[kt * 64 + k], s1p);
                s2p = fmaf(xv, g_p2[kt * 64 + k], s2p);
            }
        }

        #pragma unroll 4
        for (int k = 0; k < 64; k++) {
            float xr4[4];
            #pragma unroll
            for (int r = 0; r < 4; r++) xr4[r] = sX[tr + r][k];
            float4 b0 = *(float4*)&sB[k][tc];
            float4 b1 = *(float4*)&sB[k][tc + 4];
            float bb[8] = {b0.x, b0.y, b0.z, b0.w, b1.x, b1.y, b1.z, b1.w};
            #pragma unroll
            for (int r = 0; r < 4; r++)
                #pragma unroll
                for (int c = 0; c < 8; c++)
                    acc[r][c] += xr4[r] * bb[c];
        }
        __syncthreads();
    }

    if (tid < 64) {
        int n = n0 + tid;
        if (n < NN) { g_s1[n] = s1p; g_s2[n] = s2p; }
    }

    #pragma unroll
    for (int r = 0; r < 4; r++) {
        int n = n0 + tr + r;
        if (n < NN) {
            float4 o0 = make_float4(acc[r][0], acc[r][1], acc[r][2], acc[r][3]);
            float4 o1 = make_float4(acc[r][4], acc[r][5], acc[r][6], acc[r][7]);
            *(float4*)(g_hv + (size_t)n * 64 + tc)     = o0;
            *(float4*)(g_hv + (size_t)n * 64 + tc + 4) = o1;
        }
    }
}

// ---------------- degree histogram (4 edges per thread, int4 load) ----------
__global__ void k_count(const int* __restrict__ dst) {
    int i = blockIdx.x * 256 + threadIdx.x;
    if (i * 4 >= NE) return;
    int4 d4 = ((const int4*)dst)[i];
    atomicAdd(&g_cnt[d4.x], 1);
    atomicAdd(&g_cnt[d4.y], 1);
    atomicAdd(&g_cnt[d4.z], 1);
    atomicAdd(&g_cnt[d4.w], 1);
}

// ---------------- parallel scan, phase 1: per-block exclusive scan ----------
__global__ void __launch_bounds__(1024) k_scan1() {
    __shared__ int warpsum[32];
    int tid = threadIdx.x;
    int gid = blockIdx.x * 1024 + tid;
    int lane = tid & 31;
    int wid  = tid >> 5;

    int v = (gid < NN) ? g_cnt[gid] : 0;

    // inclusive warp scan
    int x = v;
    #pragma unroll
    for (int o = 1; o < 32; o <<= 1) {
        int y = __shfl_up_sync(0xffffffffu, x, o);
        if (lane >= o) x += y;
    }
    if (lane == 31) warpsum[wid] = x;
    __syncthreads();

    // scan of 32 warp sums by warp 0
    if (wid == 0) {
        int w = warpsum[lane];
        int xw = w;
        #pragma unroll
        for (int o = 1; o < 32; o <<= 1) {
            int y = __shfl_up_sync(0xffffffffu, xw, o);
            if (lane >= o) xw += y;
        }
        warpsum[lane] = xw - w;   // exclusive
        if (lane == 31) g_bsum[blockIdx.x] = xw;   // block total
    }
    __syncthreads();

    int excl = x - v + warpsum[wid];   // block-local exclusive prefix
    if (gid < NN) g_off[gid] = excl;
}

// ---------------- phase 2: scan the 49 block totals (one warp) ---------------
__global__ void k_scan2() {
    int lane = threadIdx.x;   // 64 threads; use first SCAN_BLOCKS lanes logically
    int v = (lane < SCAN_BLOCKS) ? g_bsum[lane] : 0;
    // inclusive scan over 64 lanes via two warps? keep single warp: 64>32.
    // use simple smem scan for 64 entries
    __shared__ int s[64];
    s[lane] = v;
    __syncthreads();
    #pragma unroll
    for (int o = 1; o < 64; o <<= 1) {
        int y = (lane >= o) ? s[lane - o] : 0;
        __syncthreads();
        s[lane] += y;
        __syncthreads();
    }
    if (lane < SCAN_BLOCKS) g_bpre[lane] = s[lane] - v;   // exclusive
    if (lane == SCAN_BLOCKS - 1) g_off[NN] = s[lane];     // total = NE
}

// ---------------- phase 3: add block prefix, materialize g_cur ---------------
__global__ void __launch_bounds__(1024) k_scan3() {
    int gid = blockIdx.x * 1024 + threadIdx.x;
    if (gid >= NN) return;
    int o = g_off[gid] + g_bpre[blockIdx.x];
    g_off[gid] = o;
    g_cur[gid] = o;
}

// ---------------- fused logit + scatter into CSR order -----------------------
__global__ void k_scatter(const float* __restrict__ td, const int* __restrict__ src,
                          const int* __restrict__ dst, const float* __restrict__ omega) {
    int i = blockIdx.x * 256 + threadIdx.x;
    if (i >= NE) return;
    float t = td[i];
    int s = src[i], d = dst[i];
    float tt;
    if (t >= 0.f && t <= 1.f) {
        float u = t * (float)TABN;
        int i0 = (int)u;
        if (i0 >= TABN) i0 = TABN - 1;
        float f = u - (float)i0;
        float v0 = g_tab[i0], v1 = g_tab[i0 + 1];
        tt = v0 + f * (v1 - v0);
    } else {
        float acc = 0.f;
        for (int j = 0; j < THALF; j++) {
            float sn, cs;
            sincosf(t * omega[j], &sn, &cs);
            acc += sn * g_q[2 * j] + cs * g_q[2 * j + 1];
        }
        tt = acc * TSCALE;
    }
    float e = g_s1[s] + g_s2[d] + tt;
    e = (e > 0.f) ? e : 0.2f * e;   // LeakyReLU(0.2)
    int pos = atomicAdd(&g_cur[d], 1);
    g_esort[pos] = e;
    g_ssort[pos] = s;
}

// ---------------- warp-per-node softmax + weighted aggregation ---------------
__global__ void k_agg(float* __restrict__ out) {
    int n = blockIdx.x * 8 + (threadIdx.x >> 5);
    int lane = threadIdx.x & 31;
    if (n >= NN) return;
    int start = g_off[n], end = g_off[n + 1];

    // pass A: max (lane-strided, coalesced)
    float m = -3.402823e38f;
    for (int k = start + lane; k < end; k += 32) m = fmaxf(m, g_esort[k]);
    #pragma unroll
    for (int o = 16; o; o >>= 1) m = fmaxf(m, __shfl_xor_sync(0xffffffffu, m, o));

    // pass B: sum of exp
    float ssum = 0.f;
    for (int k = start + lane; k < end; k += 32) ssum += __expf(g_esort[k] - m);
    #pragma unroll
    for (int o = 16; o; o >>= 1) ssum += __shfl_xor_sync(0xffffffffu, ssum, o);
    float inv = (end > start) ? 1.f / ssum : 0.f;

    // pass C: uniform broadcast loads of (e, src); gather hv rows
    float a0 = 0.f, a1 = 0.f;
    #pragma unroll 2
    for (int k = start; k < end; k++) {
        float al = __expf(g_esort[k] - m);
        int sj   = g_ssort[k];
        const float* hp = g_hv + (size_t)sj * 64;
        a0 = fmaf(al, hp[lane],      a0);
        a1 = fmaf(al, hp[lane + 32], a1);
    }
    out[(size_t)n * 64 + lane]      = a0 * inv;
    out[(size_t)n * 64 + 32 + lane] = a1 * inv;
}

// ---------------- launcher ---------------------------------------------------
extern "C" void kernel_launch(void* const* d_in, const int* in_sizes, int n_in,
                              void* d_out, int out_size) {
    const float* node_feats = (const float*)d_in[0];
    const float* time_diff  = (const float*)d_in[1];
    const int*   src        = (const int*)d_in[2];
    const int*   dst        = (const int*)d_in[3];
    const float* W          = (const float*)d_in[4];
    const float* Wv         = (const float*)d_in[5];
    const float* omega      = (const float*)d_in[6];
    const float* Wt         = (const float*)d_in[7];
    const float* a          = (const float*)d_in[8];
    float* out = (float*)d_out;

    k_setup<<<51, 256>>>(W, Wt, a, Wv, omega);
    k_hv<<<(NN + 63) / 64, 128>>>(node_feats);
    k_count<<<(NE / 4 + 255) / 256, 256>>>(dst);
    k_scan1<<<SCAN_BLOCKS, 1024>>>();
    k_scan2<<<1, 64>>>();
    k_scan3<<<SCAN_BLOCKS, 1024>>>();
    k_scatter<<<(NE + 255) / 256, 256>>>(time_diff, src, dst, omega);
    k_agg<<<(NN + 7) / 8, 256>>>(out);
}

// round 5
// speedup vs baseline: 2.0870x; 1.1251x over previous
#include <cuda_runtime.h>
#include <math.h>

#define NN 50000
#define NE 800000
#define IND 128
#define OUTD 64
#define THALF 64
#define TABN 4096
#define SCAN_BLOCKS 49   // ceil(50000 / 1024)

// sqrt(1/128)
#define TSCALE 0.08838834764831845f

// ---------------- scratch (static __device__, no allocations) ----------------
__device__ float g_p1[IND];
__device__ float g_p2[IND];
__device__ float g_q[2 * THALF];
__device__ float g_tab[TABN + 1];
__device__ float g_WvT[IND * OUTD];          // [k][c] layout
__device__ float g_s1[NN];
__device__ float g_s2[NN];
__device__ float g_hv[NN * OUTD];
__device__ float g_esort[NE];
__device__ int   g_ssort[NE];
__device__ int   g_cnt[NN];
__device__ int   g_off[NN + 1];
__device__ int   g_cur[NN];
__device__ int   g_bsum[SCAN_BLOCKS];

// ---------------- fused setup kernel (weights-only prep) ---------------------
// block 0       : p1 = W^T a1, p2 = W^T a2
// block 1       : g_q = Wt^T a3 (for out-of-range fallback)
// blocks 2..18  : temporal lookup table
// blocks 19..50 : WvT transpose
__global__ void k_setup(const float* __restrict__ W, const float* __restrict__ Wt,
                        const float* __restrict__ a, const float* __restrict__ Wv,
                        const float* __restrict__ omega) {
    int b = blockIdx.x;
    int t = threadIdx.x;

    if (b == 0) {
        if (t < 128) {
            float s = 0.f;
            #pragma unroll 8
            for (int i = 0; i < 64; i++) s += W[i * 128 + t] * a[i];
            g_p1[t] = s;
        } else {
            int k = t - 128;
            float s = 0.f;
            #pragma unroll 8
            for (int i = 0; i < 64; i++) s += W[i * 128 + k] * a[64 + i];
            g_p2[k] = s;
        }
    } else if (b == 1) {
        if (t < 128) {
            float s = 0.f;
            #pragma unroll 8
            for (int i = 0; i < 64; i++) s += Wt[i * 128 + t] * a[128 + i];
            g_q[t] = s;
        }
    } else if (b < 19) {
        __shared__ float qs[128];
        if (t < 128) {
            float s = 0.f;
            #pragma unroll 8
            for (int i = 0; i < 64; i++) s += Wt[i * 128 + t] * a[128 + i];
            qs[t] = s;
        }
        __syncthreads();
        int idx = (b - 2) * 256 + t;
        if (idx <= TABN) {
            float tt = (float)idx / (float)TABN;
            float s = 0.f;
            #pragma unroll 4
            for (int j = 0; j < THALF; j++) {
                float sn, cs;
                __sincosf(tt * omega[j], &sn, &cs);
                s += sn * qs[2 * j] + cs * qs[2 * j + 1];
            }
            g_tab[idx] = s * TSCALE;
        }
    } else {
        int j = (b - 19) * 256 + t;        // 0..8191
        int c = j & 63;
        int k = j >> 6;
        g_WvT[j] = Wv[c * 128 + k];
    }
}

// ---------------- per-node attention scalars s1/s2 (warp per node, float4) ---
__global__ void k_s12(const float* __restrict__ x) {
    int n = blockIdx.x * 8 + (threadIdx.x >> 5);
    int lane = threadIdx.x & 31;
    if (n >= NN) return;
    float4 v  = ((const float4*)(x + (size_t)n * IND))[lane];
    float4 p1 = ((const float4*)g_p1)[lane];
    float4 p2 = ((const float4*)g_p2)[lane];
    float d1 = v.x * p1.x + v.y * p1.y + v.z * p1.z + v.w * p1.w;
    float d2 = v.x * p2.x + v.y * p2.y + v.z * p2.z + v.w * p2.w;
    #pragma unroll
    for (int o = 16; o; o >>= 1) {
        d1 += __shfl_xor_sync(0xffffffffu, d1, o);
        d2 += __shfl_xor_sync(0xffffffffu, d2, o);
    }
    if (lane == 0) { g_s1[n] = d1; g_s2[n] = d2; }
}

// ---------------- hv = X @ Wv^T (tiled fp32 GEMM, 64x64 tile, 4x8/thread) ----
__global__ void __launch_bounds__(128) k_hv(const float* __restrict__ x) {
    __shared__ float sX[64][65];
    __shared__ float sB[64][64];

    int n0 = blockIdx.x * 64;
    int tid = threadIdx.x;
    int tr = (tid >> 3) * 4;
    int tc = (tid & 7) * 8;

    float acc[4][8];
    #pragma unroll
    for (int r = 0; r < 4; r++)
        #pragma unroll
        for (int c = 0; c < 8; c++) acc[r][c] = 0.f;

    for (int kt = 0; kt < 2; kt++) {
        for (int i = tid; i < 1024; i += 128) {
            int r  = i >> 4;
            int c4 = i & 15;
            int n = n0 + r;
            float4 v = (n < NN)
                ? *(const float4*)(x + (size_t)n * 128 + kt * 64 + c4 * 4)
                : make_float4(0.f, 0.f, 0.f, 0.f);
            sX[r][c4 * 4 + 0] = v.x;
            sX[r][c4 * 4 + 1] = v.y;
            sX[r][c4 * 4 + 2] = v.z;
            sX[r][c4 * 4 + 3] = v.w;
        }
        for (int i = tid; i < 1024; i += 128) {
            ((float4*)&sB[0][0])[i] = ((const float4*)(g_WvT + kt * 64 * 64))[i];
        }
        __syncthreads();

        #pragma unroll 4
        for (int k = 0; k < 64; k++) {
            float xr4[4];
            #pragma unroll
            for (int r = 0; r < 4; r++) xr4[r] = sX[tr + r][k];
            float4 b0 = *(float4*)&sB[k][tc];
            float4 b1 = *(float4*)&sB[k][tc + 4];
            float bb[8] = {b0.x, b0.y, b0.z, b0.w, b1.x, b1.y, b1.z, b1.w};
            #pragma unroll
            for (int r = 0; r < 4; r++)
                #pragma unroll
                for (int c = 0; c < 8; c++)
                    acc[r][c] += xr4[r] * bb[c];
        }
        __syncthreads();
    }

    #pragma unroll
    for (int r = 0; r < 4; r++) {
        int n = n0 + tr + r;
        if (n < NN) {
            float4 o0 = make_float4(acc[r][0], acc[r][1], acc[r][2], acc[r][3]);
            float4 o1 = make_float4(acc[r][4], acc[r][5], acc[r][6], acc[r][7]);
            *(float4*)(g_hv + (size_t)n * 64 + tc)     = o0;
            *(float4*)(g_hv + (size_t)n * 64 + tc + 4) = o1;
        }
    }
}

// ---------------- zero counters (independent branch head) --------------------
__global__ void __launch_bounds__(1024) k_zero() {
    int gid = blockIdx.x * 1024 + threadIdx.x;
    if (gid < NN) g_cnt[gid] = 0;
}

// ---------------- degree histogram (4 edges per thread, int4 load) ----------
__global__ void k_count(const int* __restrict__ dst) {
    int i = blockIdx.x * 256 + threadIdx.x;
    if (i * 4 >= NE) return;
    int4 d4 = ((const int4*)dst)[i];
    atomicAdd(&g_cnt[d4.x], 1);
    atomicAdd(&g_cnt[d4.y], 1);
    atomicAdd(&g_cnt[d4.z], 1);
    atomicAdd(&g_cnt[d4.w], 1);
}

// ---------------- scan phase 1: per-block exclusive scan ---------------------
__global__ void __launch_bounds__(1024) k_scan1() {
    __shared__ int warpsum[32];
    int tid = threadIdx.x;
    int gid = blockIdx.x * 1024 + tid;
    int lane = tid & 31;
    int wid  = tid >> 5;

    int v = (gid < NN) ? g_cnt[gid] : 0;

    int x = v;
    #pragma unroll
    for (int o = 1; o < 32; o <<= 1) {
        int y = __shfl_up_sync(0xffffffffu, x, o);
        if (lane >= o) x += y;
    }
    if (lane == 31) warpsum[wid] = x;
    __syncthreads();

    if (wid == 0) {
        int w = warpsum[lane];
        int xw = w;
        #pragma unroll
        for (int o = 1; o < 32; o <<= 1) {
            int y = __shfl_up_sync(0xffffffffu, xw, o);
            if (lane >= o) xw += y;
        }
        warpsum[lane] = xw - w;
        if (lane == 31) g_bsum[blockIdx.x] = xw;
    }
    __syncthreads();

    int excl = x - v + warpsum[wid];
    if (gid < NN) g_off[gid] = excl;
}

// ---------------- scan phase 2+3 fused: add block prefix, fill g_cur ---------
__global__ void __launch_bounds__(1024) k_scan23() {
    __shared__ int spre;
    int b = blockIdx.x;
    if (threadIdx.x < 32) {
        int lane = threadIdx.x;
        int acc = 0;
        for (int j = lane; j < b; j += 32) acc += g_bsum[j];
        #pragma unroll
        for (int o = 16; o; o >>= 1) acc += __shfl_xor_sync(0xffffffffu, acc, o);
        if (lane == 0) spre = acc;
    }
    __syncthreads();
    int gid = b * 1024 + threadIdx.x;
    if (gid < NN) {
        int o = g_off[gid] + spre;
        g_off[gid] = o;
        g_cur[gid] = o;
    }
    if (b == 0 && threadIdx.x == 0) g_off[NN] = NE;   // counts always sum to NE
}

// ---------------- fused logit + scatter into CSR order (2 edges/thread) ------
__global__ void k_scatter(const float* __restrict__ td, const int* __restrict__ src,
                          const int* __restrict__ dst, const float* __restrict__ omega) {
    int i = blockIdx.x * 256 + threadIdx.x;
    if (i * 2 >= NE) return;
    float2 t2 = ((const float2*)td)[i];
    int2   s2 = ((const int2*)src)[i];
    int2   d2 = ((const int2*)dst)[i];

    #pragma unroll
    for (int j = 0; j < 2; j++) {
        float t = (j == 0) ? t2.x : t2.y;
        int s   = (j == 0) ? s2.x : s2.y;
        int d   = (j == 0) ? d2.x : d2.y;
        float tt;
        if (t >= 0.f && t <= 1.f) {
            float u = t * (float)TABN;
            int i0 = (int)u;
            if (i0 >= TABN) i0 = TABN - 1;
            float f = u - (float)i0;
            float v0 = g_tab[i0], v1 = g_tab[i0 + 1];
            tt = v0 + f * (v1 - v0);
        } else {
            float acc = 0.f;
            for (int jj = 0; jj < THALF; jj++) {
                float sn, cs;
                sincosf(t * omega[jj], &sn, &cs);
                acc += sn * g_q[2 * jj] + cs * g_q[2 * jj + 1];
            }
            tt = acc * TSCALE;
        }
        float e = g_s1[s] + g_s2[d] + tt;
        e = (e > 0.f) ? e : 0.2f * e;   // LeakyReLU(0.2)
        int pos = atomicAdd(&g_cur[d], 1);
        g_esort[pos] = e;
        g_ssort[pos] = s;
    }
}

// ---------------- warp-per-node softmax + weighted aggregation ---------------
__global__ void k_agg(float* __restrict__ out) {
    int n = blockIdx.x * 8 + (threadIdx.x >> 5);
    int lane = threadIdx.x & 31;
    if (n >= NN) return;
    int start = g_off[n], end = g_off[n + 1];

    // pass A: max (lane-strided, coalesced)
    float m = -3.402823e38f;
    for (int k = start + lane; k < end; k += 32) m = fmaxf(m, g_esort[k]);
    #pragma unroll
    for (int o = 16; o; o >>= 1) m = fmaxf(m, __shfl_xor_sync(0xffffffffu, m, o));

    // pass B: sum of exp
    float ssum = 0.f;
    for (int k = start + lane; k < end; k += 32) ssum += __expf(g_esort[k] - m);
    #pragma unroll
    for (int o = 16; o; o >>= 1) ssum += __shfl_xor_sync(0xffffffffu, ssum, o);
    float inv = (end > start) ? 1.f / ssum : 0.f;

    // pass C: 4-wide unrolled gather-accumulate, float2 per lane
    float ax = 0.f, ay = 0.f;
    int k = start;
    for (; k + 4 <= end; k += 4) {
        float e0 = g_esort[k],     e1 = g_esort[k + 1];
        float e2 = g_esort[k + 2], e3 = g_esort[k + 3];
        int   j0 = g_ssort[k],     j1 = g_ssort[k + 1];
        int   j2 = g_ssort[k + 2], j3 = g_ssort[k + 3];
        float2 v0 = ((const float2*)(g_hv + (size_t)j0 * 64))[lane];
        float2 v1 = ((const float2*)(g_hv + (size_t)j1 * 64))[lane];
        float2 v2 = ((const float2*)(g_hv + (size_t)j2 * 64))[lane];
        float2 v3 = ((const float2*)(g_hv + (size_t)j3 * 64))[lane];
        float w0 = __expf(e0 - m), w1 = __expf(e1 - m);
        float w2 = __expf(e2 - m), w3 = __expf(e3 - m);
        ax = fmaf(w0, v0.x, ax); ay = fmaf(w0, v0.y, ay);
        ax = fmaf(w1, v1.x, ax); ay = fmaf(w1, v1.y, ay);
        ax = fmaf(w2, v2.x, ax); ay = fmaf(w2, v2.y, ay);
        ax = fmaf(w3, v3.x, ax); ay = fmaf(w3, v3.y, ay);
    }
    for (; k < end; k++) {
        float w = __expf(g_esort[k] - m);
        float2 v = ((const float2*)(g_hv + (size_t)g_ssort[k] * 64))[lane];
        ax = fmaf(w, v.x, ax);
        ay = fmaf(w, v.y, ay);
    }
    float2 o2 = make_float2(ax * inv, ay * inv);
    ((float2*)(out + (size_t)n * 64))[lane] = o2;
}

// ---------------- launcher: forked-graph capture -----------------------------
extern "C" void kernel_launch(void* const* d_in, const int* in_sizes, int n_in,
                              void* d_out, int out_size) {
    const float* node_feats = (const float*)d_in[0];
    const float* time_diff  = (const float*)d_in[1];
    const int*   src        = (const int*)d_in[2];
    const int*   dst        = (const int*)d_in[3];
    const float* W          = (const float*)d_in[4];
    const float* Wv         = (const float*)d_in[5];
    const float* omega      = (const float*)d_in[6];
    const float* Wt         = (const float*)d_in[7];
    const float* a          = (const float*)d_in[8];
    float* out = (float*)d_out;

    // lazily-created side streams + events (resources only; work is identical
    // and fully re-issued on every call)
    static cudaStream_t sB = nullptr, sC = nullptr;
    static cudaEvent_t evFork = nullptr, evSetup = nullptr, evScan = nullptr, evHv = nullptr;
    if (!sB) {
        cudaStreamCreateWithFlags(&sB, cudaStreamNonBlocking);
        cudaStreamCreateWithFlags(&sC, cudaStreamNonBlocking);
        cudaEventCreateWithFlags(&evFork,  cudaEventDisableTiming);
        cudaEventCreateWithFlags(&evSetup, cudaEventDisableTiming);
        cudaEventCreateWithFlags(&evScan,  cudaEventDisableTiming);
        cudaEventCreateWithFlags(&evHv,    cudaEventDisableTiming);
    }

    // fork side branch B (CSR build: depends only on dst)
    cudaEventRecord(evFork, 0);
    cudaStreamWaitEvent(sB, evFork, 0);
    k_zero  <<<SCAN_BLOCKS, 1024, 0, sB>>>();
    k_count <<<(NE / 4 + 255) / 256, 256, 0, sB>>>(dst);
    k_scan1 <<<SCAN_BLOCKS, 1024, 0, sB>>>();
    k_scan23<<<SCAN_BLOCKS, 1024, 0, sB>>>();
    cudaEventRecord(evScan, sB);

    // main: weight prep, then per-node scalars
    k_setup<<<51, 256>>>(W, Wt, a, Wv, omega);
    cudaEventRecord(evSetup, 0);

    // branch C: value projection GEMM (needs WvT from setup)
    cudaStreamWaitEvent(sC, evSetup, 0);
    k_hv<<<(NN + 63) / 64, 128, 0, sC>>>(node_feats);
    cudaEventRecord(evHv, sC);

    // main continues
    k_s12<<<(NN + 7) / 8, 256>>>(node_feats);
    cudaStreamWaitEvent(0, evScan, 0);
    k_scatter<<<(NE / 2 + 255) / 256, 256>>>(time_diff, src, dst, omega);
    cudaStreamWaitEvent(0, evHv, 0);
    k_agg<<<(NN + 7) / 8, 256>>>(out);
}

// round 6
// speedup vs baseline: 2.1940x; 1.0513x over previous
#include <cuda_runtime.h>
#include <math.h>

#define NN 50000
#define NE 800000
#define IND 128
#define OUTD 64
#define THALF 64
#define TABN 4096
#define SCAN_BLOCKS 49   // ceil(50000 / 1024)

// sqrt(1/128)
#define TSCALE 0.08838834764831845f

// ---------------- scratch (static __device__, no allocations) ----------------
__device__ float g_p1[IND];
__device__ float g_p2[IND];
__device__ float g_q[2 * THALF];
__device__ float g_tab[TABN + 1];
__device__ float g_WvT[IND * OUTD];          // [k][c] layout
__device__ float g_s1[NN];
__device__ float g_s2[NN];
__device__ float g_hv[NN * OUTD];
__device__ float2 g_pair[NE];                // (w=exp(leaky(e)), bitcast(src))
__device__ int   g_cnt[NN];
__device__ int   g_off[NN + 1];
__device__ int   g_cur[NN];
__device__ int   g_bsum[SCAN_BLOCKS];

// ---------------- fused setup kernel (weights-only prep) ---------------------
__global__ void k_setup(const float* __restrict__ W, const float* __restrict__ Wt,
                        const float* __restrict__ a, const float* __restrict__ Wv,
                        const float* __restrict__ omega) {
    int b = blockIdx.x;
    int t = threadIdx.x;

    if (b == 0) {
        if (t < 128) {
            float s = 0.f;
            #pragma unroll 8
            for (int i = 0; i < 64; i++) s += W[i * 128 + t] * a[i];
            g_p1[t] = s;
        } else {
            int k = t - 128;
            float s = 0.f;
            #pragma unroll 8
            for (int i = 0; i < 64; i++) s += W[i * 128 + k] * a[64 + i];
            g_p2[k] = s;
        }
    } else if (b == 1) {
        if (t < 128) {
            float s = 0.f;
            #pragma unroll 8
            for (int i = 0; i < 64; i++) s += Wt[i * 128 + t] * a[128 + i];
            g_q[t] = s;
        }
    } else if (b < 19) {
        __shared__ float qs[128];
        if (t < 128) {
            float s = 0.f;
            #pragma unroll 8
            for (int i = 0; i < 64; i++) s += Wt[i * 128 + t] * a[128 + i];
            qs[t] = s;
        }
        __syncthreads();
        int idx = (b - 2) * 256 + t;
        if (idx <= TABN) {
            float tt = (float)idx / (float)TABN;
            float s = 0.f;
            #pragma unroll 4
            for (int j = 0; j < THALF; j++) {
                float sn, cs;
                __sincosf(tt * omega[j], &sn, &cs);
                s += sn * qs[2 * j] + cs * qs[2 * j + 1];
            }
            g_tab[idx] = s * TSCALE;
        }
    } else {
        int j = (b - 19) * 256 + t;        // 0..8191
        int c = j & 63;
        int k = j >> 6;
        g_WvT[j] = Wv[c * 128 + k];
    }
}

// ---------------- hv = X @ Wv^T + fused s1/s2 --------------------------------
__global__ void __launch_bounds__(128) k_hv(const float* __restrict__ x) {
    __shared__ float sX[64][68];   // row stride 68 floats = 272B (16B aligned)
    __shared__ float sB[64][64];

    int n0 = blockIdx.x * 64;
    int tid = threadIdx.x;
    int tr = (tid >> 3) * 4;
    int tc = (tid & 7) * 8;

    float acc[4][8];
    #pragma unroll
    for (int r = 0; r < 4; r++)
        #pragma unroll
        for (int c = 0; c < 8; c++) acc[r][c] = 0.f;

    float s1p = 0.f, s2p = 0.f;

    #pragma unroll
    for (int kt = 0; kt < 2; kt++) {
        for (int i = tid; i < 1024; i += 128) {
            int r  = i >> 4;
            int c4 = i & 15;
            int n = n0 + r;
            float4 v = (n < NN)
                ? *(const float4*)(x + (size_t)n * 128 + kt * 64 + c4 * 4)
                : make_float4(0.f, 0.f, 0.f, 0.f);
            *(float4*)&sX[r][c4 * 4] = v;
        }
        for (int i = tid; i < 1024; i += 128) {
            ((float4*)&sB[0][0])[i] = ((const float4*)(g_WvT + kt * 64 * 64))[i];
        }
        __syncthreads();

        // fused per-node attention scalars (threads 0..63, one row each)
        if (tid < 64) {
            #pragma unroll 8
            for (int k = 0; k < 64; k++) {
                float xv = sX[tid][k];
                s1p = fmaf(xv, g_p1[kt * 64 + k], s1p);
                s2p = fmaf(xv, g_p2[kt * 64 + k], s2p);
            }
        }

        #pragma unroll 4
        for (int kk = 0; kk < 64; kk += 4) {
            float4 xr[4];
            #pragma unroll
            for (int r = 0; r < 4; r++) xr[r] = *(float4*)&sX[tr + r][kk];
            #pragma unroll
            for (int u = 0; u < 4; u++) {
                float4 b0 = *(float4*)&sB[kk + u][tc];
                float4 b1 = *(float4*)&sB[kk + u][tc + 4];
                float bb[8] = {b0.x, b0.y, b0.z, b0.w, b1.x, b1.y, b1.z, b1.w};
                #pragma unroll
                for (int r = 0; r < 4; r++) {
                    float xv = (u == 0) ? xr[r].x : (u == 1) ? xr[r].y
                             : (u == 2) ? xr[r].z : xr[r].w;
                    #pragma unroll
                    for (int c = 0; c < 8; c++)
                        acc[r][c] = fmaf(xv, bb[c], acc[r][c]);
                }
            }
        }
        __syncthreads();
    }

    if (tid < 64) {
        int n = n0 + tid;
        if (n < NN) { g_s1[n] = s1p; g_s2[n] = s2p; }
    }

    #pragma unroll
    for (int r = 0; r < 4; r++) {
        int n = n0 + tr + r;
        if (n < NN) {
            float4 o0 = make_float4(acc[r][0], acc[r][1], acc[r][2], acc[r][3]);
            float4 o1 = make_float4(acc[r][4], acc[r][5], acc[r][6], acc[r][7]);
            *(float4*)(g_hv + (size_t)n * 64 + tc)     = o0;
            *(float4*)(g_hv + (size_t)n * 64 + tc + 4) = o1;
        }
    }
}

// ---------------- zero counters (independent branch head) --------------------
__global__ void __launch_bounds__(1024) k_zero() {
    int gid = blockIdx.x * 1024 + threadIdx.x;
    if (gid < NN) g_cnt[gid] = 0;
}

// ---------------- degree histogram (4 edges per thread, int4 load) ----------
__global__ void k_count(const int* __restrict__ dst) {
    int i = blockIdx.x * 256 + threadIdx.x;
    if (i * 4 >= NE) return;
    int4 d4 = ((const int4*)dst)[i];
    atomicAdd(&g_cnt[d4.x], 1);
    atomicAdd(&g_cnt[d4.y], 1);
    atomicAdd(&g_cnt[d4.z], 1);
    atomicAdd(&g_cnt[d4.w], 1);
}

// ---------------- scan phase 1: per-block exclusive scan ---------------------
__global__ void __launch_bounds__(1024) k_scan1() {
    __shared__ int warpsum[32];
    int tid = threadIdx.x;
    int gid = blockIdx.x * 1024 + tid;
    int lane = tid & 31;
    int wid  = tid >> 5;

    int v = (gid < NN) ? g_cnt[gid] : 0;

    int x = v;
    #pragma unroll
    for (int o = 1; o < 32; o <<= 1) {
        int y = __shfl_up_sync(0xffffffffu, x, o);
        if (lane >= o) x += y;
    }
    if (lane == 31) warpsum[wid] = x;
    __syncthreads();

    if (wid == 0) {
        int w = warpsum[lane];
        int xw = w;
        #pragma unroll
        for (int o = 1; o < 32; o <<= 1) {
            int y = __shfl_up_sync(0xffffffffu, xw, o);
            if (lane >= o) xw += y;
        }
        warpsum[lane] = xw - w;
        if (lane == 31) g_bsum[blockIdx.x] = xw;
    }
    __syncthreads();

    int excl = x - v + warpsum[wid];
    if (gid < NN) g_off[gid] = excl;
}

// ---------------- scan phase 2+3 fused: add block prefix, fill g_cur ---------
__global__ void __launch_bounds__(1024) k_scan23() {
    __shared__ int spre;
    int b = blockIdx.x;
    if (threadIdx.x < 32) {
        int lane = threadIdx.x;
        int acc = 0;
        for (int j = lane; j < b; j += 32) acc += g_bsum[j];
        #pragma unroll
        for (int o = 16; o; o >>= 1) acc += __shfl_xor_sync(0xffffffffu, acc, o);
        if (lane == 0) spre = acc;
    }
    __syncthreads();
    int gid = b * 1024 + threadIdx.x;
    if (gid < NN) {
        int o = g_off[gid] + spre;
        g_off[gid] = o;
        g_cur[gid] = o;
    }
    if (b == 0 && threadIdx.x == 0) g_off[NN] = NE;   // counts sum to NE
}

// ---------------- fused logit + exp + scatter into CSR (2 edges/thread) ------
__global__ void k_scatter(const float* __restrict__ td, const int* __restrict__ src,
                          const int* __restrict__ dst, const float* __restrict__ omega) {
    int i = blockIdx.x * 256 + threadIdx.x;
    if (i * 2 >= NE) return;
    float2 t2 = ((const float2*)td)[i];
    int2   s2 = ((const int2*)src)[i];
    int2   d2 = ((const int2*)dst)[i];

    #pragma unroll
    for (int j = 0; j < 2; j++) {
        float t = (j == 0) ? t2.x : t2.y;
        int s   = (j == 0) ? s2.x : s2.y;
        int d   = (j == 0) ? d2.x : d2.y;
        float tt;
        if (t >= 0.f && t <= 1.f) {
            float u = t * (float)TABN;
            int i0 = (int)u;
            if (i0 >= TABN) i0 = TABN - 1;
            float f = u - (float)i0;
            float v0 = g_tab[i0], v1 = g_tab[i0 + 1];
            tt = v0 + f * (v1 - v0);
        } else {
            float acc = 0.f;
            for (int jj = 0; jj < THALF; jj++) {
                float sn, cs;
                sincosf(t * omega[jj], &sn, &cs);
                acc += sn * g_q[2 * jj] + cs * g_q[2 * jj + 1];
            }
            tt = acc * TSCALE;
        }
        float e = g_s1[s] + g_s2[d] + tt;
        e = (e > 0.f) ? e : 0.2f * e;       // LeakyReLU(0.2)
        float w = __expf(e);                // softmax numerator (logits are O(1))
        int pos = atomicAdd(&g_cur[d], 1);
        g_pair[pos] = make_float2(w, __int_as_float(s));
    }
}

// ---------------- warp-per-node single-pass softmax-aggregate ----------------
__global__ void k_agg(float* __restrict__ out) {
    int n = blockIdx.x * 8 + (threadIdx.x >> 5);
    int lane = threadIdx.x & 31;
    if (n >= NN) return;
    int start = g_off[n], end = g_off[n + 1];

    float wsum = 0.f, ax = 0.f, ay = 0.f;
    int k = start;
    for (; k + 4 <= end; k += 4) {
        float2 p0 = g_pair[k],     p1 = g_pair[k + 1];
        float2 p2 = g_pair[k + 2], p3 = g_pair[k + 3];
        int j0 = __float_as_int(p0.y), j1 = __float_as_int(p1.y);
        int j2 = __float_as_int(p2.y), j3 = __float_as_int(p3.y);
        float2 v0 = ((const float2*)(g_hv + (size_t)j0 * 64))[lane];
        float2 v1 = ((const float2*)(g_hv + (size_t)j1 * 64))[lane];
        float2 v2 = ((const float2*)(g_hv + (size_t)j2 * 64))[lane];
        float2 v3 = ((const float2*)(g_hv + (size_t)j3 * 64))[lane];
        wsum += (p0.x + p1.x) + (p2.x + p3.x);
        ax = fmaf(p0.x, v0.x, ax); ay = fmaf(p0.x, v0.y, ay);
        ax = fmaf(p1.x, v1.x, ax); ay = fmaf(p1.x, v1.y, ay);
        ax = fmaf(p2.x, v2.x, ax); ay = fmaf(p2.x, v2.y, ay);
        ax = fmaf(p3.x, v3.x, ax); ay = fmaf(p3.x, v3.y, ay);
    }
    for (; k < end; k++) {
        float2 p = g_pair[k];
        float2 v = ((const float2*)(g_hv + (size_t)__float_as_int(p.y) * 64))[lane];
        wsum += p.x;
        ax = fmaf(p.x, v.x, ax);
        ay = fmaf(p.x, v.y, ay);
    }
    float inv = (end > start) ? 1.f / wsum : 0.f;
    ((float2*)(out + (size_t)n * 64))[lane] = make_float2(ax * inv, ay * inv);
}

// ---------------- launcher: CSR branch forked off main chain -----------------
extern "C" void kernel_launch(void* const* d_in, const int* in_sizes, int n_in,
                              void* d_out, int out_size) {
    const float* node_feats = (const float*)d_in[0];
    const float* time_diff  = (const float*)d_in[1];
    const int*   src        = (const int*)d_in[2];
    const int*   dst        = (const int*)d_in[3];
    const float* W          = (const float*)d_in[4];
    const float* Wv         = (const float*)d_in[5];
    const float* omega      = (const float*)d_in[6];
    const float* Wt         = (const float*)d_in[7];
    const float* a          = (const float*)d_in[8];
    float* out = (float*)d_out;

    static cudaStream_t sB = nullptr;
    static cudaEvent_t evFork = nullptr, evScan = nullptr;
    if (!sB) {
        cudaStreamCreateWithFlags(&sB, cudaStreamNonBlocking);
        cudaEventCreateWithFlags(&evFork, cudaEventDisableTiming);
        cudaEventCreateWithFlags(&evScan, cudaEventDisableTiming);
    }

    // side branch: CSR build (depends only on dst)
    cudaEventRecord(evFork, 0);
    cudaStreamWaitEvent(sB, evFork, 0);
    k_zero  <<<SCAN_BLOCKS, 1024, 0, sB>>>();
    k_count <<<(NE / 4 + 255) / 256, 256, 0, sB>>>(dst);
    k_scan1 <<<SCAN_BLOCKS, 1024, 0, sB>>>();
    k_scan23<<<SCAN_BLOCKS, 1024, 0, sB>>>();
    cudaEventRecord(evScan, sB);

    // main chain
    k_setup<<<51, 256>>>(W, Wt, a, Wv, omega);
    k_hv<<<(NN + 63) / 64, 128>>>(node_feats);
    cudaStreamWaitEvent(0, evScan, 0);
    k_scatter<<<(NE / 2 + 255) / 256, 256>>>(time_diff, src, dst, omega);
    k_agg<<<(NN + 7) / 8, 256>>>(out);
}

// round 7
// speedup vs baseline: 2.3375x; 1.0654x over previous
#include <cuda_runtime.h>
#include <cuda_fp16.h>
#include <math.h>

#define NN 50000
#define NE 800000
#define IND 128
#define OUTD 64
#define THALF 64
#define TABN 4096
#define SCAN_BLOCKS 49   // ceil(50000 / 1024)

// sqrt(1/128)
#define TSCALE 0.08838834764831845f

// ---------------- scratch (static __device__, no allocations) ----------------
__device__ float  g_p1[IND];
__device__ float  g_p2[IND];
__device__ float  g_q[2 * THALF];
__device__ float  g_tab[TABN + 1];
__device__ float  g_WvT[IND * OUTD];          // [k][c] layout
__device__ float  g_s1[NN];
__device__ float  g_s2[NN];
__device__ __half g_hv[NN * OUTD];            // fp16 value rows (halves gather BW)
__device__ float2 g_pair[NE];                 // (w=exp(leaky(e)), bitcast(src))
__device__ int    g_cnt[NN];
__device__ int    g_off[NN + 1];
__device__ int    g_cur[NN];
__device__ int    g_bsum[SCAN_BLOCKS];

// ---------------- packed f32x2 helpers ---------------------------------------
__device__ __forceinline__ unsigned long long fma2(unsigned long long a,
                                                   unsigned long long b,
                                                   unsigned long long c) {
    unsigned long long d;
    asm("fma.rn.f32x2 %0, %1, %2, %3;" : "=l"(d) : "l"(a), "l"(b), "l"(c));
    return d;
}
__device__ __forceinline__ unsigned long long splat2(float x) {
    unsigned long long d;
    asm("mov.b64 %0, {%1, %1};" : "=l"(d) : "f"(x));
    return d;
}
__device__ __forceinline__ float2 unpack2(unsigned long long v) {
    float lo, hi;
    asm("mov.b64 {%0, %1}, %2;" : "=f"(lo), "=f"(hi) : "l"(v));
    return make_float2(lo, hi);
}

// ---------------- fused setup kernel (weights-only prep) ---------------------
__global__ void k_setup(const float* __restrict__ W, const float* __restrict__ Wt,
                        const float* __restrict__ a, const float* __restrict__ Wv,
                        const float* __restrict__ omega) {
    int b = blockIdx.x;
    int t = threadIdx.x;

    if (b == 0) {
        if (t < 128) {
            float s = 0.f;
            #pragma unroll 8
            for (int i = 0; i < 64; i++) s += W[i * 128 + t] * a[i];
            g_p1[t] = s;
        } else {
            int k = t - 128;
            float s = 0.f;
            #pragma unroll 8
            for (int i = 0; i < 64; i++) s += W[i * 128 + k] * a[64 + i];
            g_p2[k] = s;
        }
    } else if (b == 1) {
        if (t < 128) {
            float s = 0.f;
            #pragma unroll 8
            for (int i = 0; i < 64; i++) s += Wt[i * 128 + t] * a[128 + i];
            g_q[t] = s;
        }
    } else if (b < 19) {
        __shared__ float qs[128];
        if (t < 128) {
            float s = 0.f;
            #pragma unroll 8
            for (int i = 0; i < 64; i++) s += Wt[i * 128 + t] * a[128 + i];
            qs[t] = s;
        }
        __syncthreads();
        int idx = (b - 2) * 256 + t;
        if (idx <= TABN) {
            float tt = (float)idx / (float)TABN;
            float s = 0.f;
            #pragma unroll 4
            for (int j = 0; j < THALF; j++) {
                float sn, cs;
                __sincosf(tt * omega[j], &sn, &cs);
                s += sn * qs[2 * j] + cs * qs[2 * j + 1];
            }
            g_tab[idx] = s * TSCALE;
        }
    } else {
        int j = (b - 19) * 256 + t;        // 0..8191
        int c = j & 63;
        int k = j >> 6;
        g_WvT[j] = Wv[c * 128 + k];
    }
}

// ---------------- per-node attention scalars s1/s2 (warp per node) -----------
__global__ void k_s12(const float* __restrict__ x) {
    int n = blockIdx.x * 8 + (threadIdx.x >> 5);
    int lane = threadIdx.x & 31;
    if (n >= NN) return;
    float4 v  = ((const float4*)(x + (size_t)n * IND))[lane];
    float4 p1 = ((const float4*)g_p1)[lane];
    float4 p2 = ((const float4*)g_p2)[lane];
    float d1 = v.x * p1.x + v.y * p1.y + v.z * p1.z + v.w * p1.w;
    float d2 = v.x * p2.x + v.y * p2.y + v.z * p2.z + v.w * p2.w;
    #pragma unroll
    for (int o = 16; o; o >>= 1) {
        d1 += __shfl_xor_sync(0xffffffffu, d1, o);
        d2 += __shfl_xor_sync(0xffffffffu, d2, o);
    }
    if (lane == 0) { g_s1[n] = d1; g_s2[n] = d2; }
}

// ---------------- hv = X @ Wv^T (packed f32x2 GEMM, fp16 output) -------------
__global__ void __launch_bounds__(128) k_hv(const float* __restrict__ x) {
    __shared__ float sX[64][68];   // row stride 68 floats (16B aligned, no conflicts)
    __shared__ float sB[64][64];

    int n0 = blockIdx.x * 64;
    int tid = threadIdx.x;
    int tr = (tid >> 3) * 4;
    int tc = (tid & 7) * 8;

    unsigned long long acc[4][4];  // [row][col-pair], 2 fp32 per entry
    #pragma unroll
    for (int r = 0; r < 4; r++)
        #pragma unroll
        for (int c = 0; c < 4; c++) acc[r][c] = 0ull;

    #pragma unroll
    for (int kt = 0; kt < 2; kt++) {
        for (int i = tid; i < 1024; i += 128) {
            int r  = i >> 4;
            int c4 = i & 15;
            int n = n0 + r;
            float4 v = (n < NN)
                ? *(const float4*)(x + (size_t)n * 128 + kt * 64 + c4 * 4)
                : make_float4(0.f, 0.f, 0.f, 0.f);
            *(float4*)&sX[r][c4 * 4] = v;
        }
        for (int i = tid; i < 1024; i += 128) {
            ((float4*)&sB[0][0])[i] = ((const float4*)(g_WvT + kt * 64 * 64))[i];
        }
        __syncthreads();

        #pragma unroll 4
        for (int kk = 0; kk < 64; kk += 4) {
            float4 xr[4];
            #pragma unroll
            for (int r = 0; r < 4; r++) xr[r] = *(float4*)&sX[tr + r][kk];
            #pragma unroll
            for (int u = 0; u < 4; u++) {
                ulonglong2 bp0 = *(ulonglong2*)&sB[kk + u][tc];      // cols tc..tc+3
                ulonglong2 bp1 = *(ulonglong2*)&sB[kk + u][tc + 4];  // cols tc+4..tc+7
                #pragma unroll
                for (int r = 0; r < 4; r++) {
                    float xv = (u == 0) ? xr[r].x : (u == 1) ? xr[r].y
                             : (u == 2) ? xr[r].z : xr[r].w;
                    unsigned long long xs = splat2(xv);
                    acc[r][0] = fma2(xs, bp0.x, acc[r][0]);
                    acc[r][1] = fma2(xs, bp0.y, acc[r][1]);
                    acc[r][2] = fma2(xs, bp1.x, acc[r][2]);
                    acc[r][3] = fma2(xs, bp1.y, acc[r][3]);
                }
            }
        }
        __syncthreads();
    }

    #pragma unroll
    for (int r = 0; r < 4; r++) {
        int n = n0 + tr + r;
        if (n < NN) {
            __half2 h[4];
            #pragma unroll
            for (int c = 0; c < 4; c++) {
                float2 f = unpack2(acc[r][c]);
                h[c] = __floats2half2_rn(f.x, f.y);
            }
            *(uint4*)(g_hv + (size_t)n * 64 + tc) =
                make_uint4(*(unsigned*)&h[0], *(unsigned*)&h[1],
                           *(unsigned*)&h[2], *(unsigned*)&h[3]);
        }
    }
}

// ---------------- zero counters (independent branch head) --------------------
__global__ void __launch_bounds__(1024) k_zero() {
    int gid = blockIdx.x * 1024 + threadIdx.x;
    if (gid < NN) g_cnt[gid] = 0;
}

// ---------------- degree histogram (4 edges per thread, int4 load) ----------
__global__ void k_count(const int* __restrict__ dst) {
    int i = blockIdx.x * 256 + threadIdx.x;
    if (i * 4 >= NE) return;
    int4 d4 = ((const int4*)dst)[i];
    atomicAdd(&g_cnt[d4.x], 1);
    atomicAdd(&g_cnt[d4.y], 1);
    atomicAdd(&g_cnt[d4.z], 1);
    atomicAdd(&g_cnt[d4.w], 1);
}

// ---------------- scan phase 1: per-block exclusive scan ---------------------
__global__ void __launch_bounds__(1024) k_scan1() {
    __shared__ int warpsum[32];
    int tid = threadIdx.x;
    int gid = blockIdx.x * 1024 + tid;
    int lane = tid & 31;
    int wid  = tid >> 5;

    int v = (gid < NN) ? g_cnt[gid] : 0;

    int x = v;
    #pragma unroll
    for (int o = 1; o < 32; o <<= 1) {
        int y = __shfl_up_sync(0xffffffffu, x, o);
        if (lane >= o) x += y;
    }
    if (lane == 31) warpsum[wid] = x;
    __syncthreads();

    if (wid == 0) {
        int w = warpsum[lane];
        int xw = w;
        #pragma unroll
        for (int o = 1; o < 32; o <<= 1) {
            int y = __shfl_up_sync(0xffffffffu, xw, o);
            if (lane >= o) xw += y;
        }
        warpsum[lane] = xw - w;
        if (lane == 31) g_bsum[blockIdx.x] = xw;
    }
    __syncthreads();

    int excl = x - v + warpsum[wid];
    if (gid < NN) g_off[gid] = excl;
}

// ---------------- scan phase 2+3 fused: add block prefix, fill g_cur ---------
__global__ void __launch_bounds__(1024) k_scan23() {
    __shared__ int spre;
    int b = blockIdx.x;
    if (threadIdx.x < 32) {
        int lane = threadIdx.x;
        int acc = 0;
        for (int j = lane; j < b; j += 32) acc += g_bsum[j];
        #pragma unroll
        for (int o = 16; o; o >>= 1) acc += __shfl_xor_sync(0xffffffffu, acc, o);
        if (lane == 0) spre = acc;
    }
    __syncthreads();
    int gid = b * 1024 + threadIdx.x;
    if (gid < NN) {
        int o = g_off[gid] + spre;
        g_off[gid] = o;
        g_cur[gid] = o;
    }
    if (b == 0 && threadIdx.x == 0) g_off[NN] = NE;   // counts sum to NE
}

// ---------------- fused logit + exp + scatter into CSR (2 edges/thread) ------
__global__ void k_scatter(const float* __restrict__ td, const int* __restrict__ src,
                          const int* __restrict__ dst, const float* __restrict__ omega) {
    int i = blockIdx.x * 256 + threadIdx.x;
    if (i * 2 >= NE) return;
    float2 t2 = ((const float2*)td)[i];
    int2   s2 = ((const int2*)src)[i];
    int2   d2 = ((const int2*)dst)[i];

    #pragma unroll
    for (int j = 0; j < 2; j++) {
        float t = (j == 0) ? t2.x : t2.y;
        int s   = (j == 0) ? s2.x : s2.y;
        int d   = (j == 0) ? d2.x : d2.y;
        float tt;
        if (t >= 0.f && t <= 1.f) {
            float u = t * (float)TABN;
            int i0 = (int)u;
            if (i0 >= TABN) i0 = TABN - 1;
            float f = u - (float)i0;
            float v0 = g_tab[i0], v1 = g_tab[i0 + 1];
            tt = v0 + f * (v1 - v0);
        } else {
            float acc = 0.f;
            for (int jj = 0; jj < THALF; jj++) {
                float sn, cs;
                sincosf(t * omega[jj], &sn, &cs);
                acc += sn * g_q[2 * jj] + cs * g_q[2 * jj + 1];
            }
            tt = acc * TSCALE;
        }
        float e = g_s1[s] + g_s2[d] + tt;
        e = (e > 0.f) ? e : 0.2f * e;       // LeakyReLU(0.2)
        float w = __expf(e);                // softmax numerator (logits are O(1))
        int pos = atomicAdd(&g_cur[d], 1);
        g_pair[pos] = make_float2(w, __int_as_float(s));
    }
}

// ---------------- warp-per-node single-pass softmax-aggregate ----------------
__global__ void k_agg(float* __restrict__ out) {
    int n = blockIdx.x * 8 + (threadIdx.x >> 5);
    int lane = threadIdx.x & 31;
    if (n >= NN) return;
    int start = g_off[n], end = g_off[n + 1];

    float wsum = 0.f, ax = 0.f, ay = 0.f;
    int k = start;
    for (; k + 4 <= end; k += 4) {
        float2 p0 = g_pair[k],     p1 = g_pair[k + 1];
        float2 p2 = g_pair[k + 2], p3 = g_pair[k + 3];
        int j0 = __float_as_int(p0.y), j1 = __float_as_int(p1.y);
        int j2 = __float_as_int(p2.y), j3 = __float_as_int(p3.y);
        __half2 h0 = ((const __half2*)(g_hv + (size_t)j0 * 64))[lane];
        __half2 h1 = ((const __half2*)(g_hv + (size_t)j1 * 64))[lane];
        __half2 h2 = ((const __half2*)(g_hv + (size_t)j2 * 64))[lane];
        __half2 h3 = ((const __half2*)(g_hv + (size_t)j3 * 64))[lane];
        float2 v0 = __half22float2(h0), v1 = __half22float2(h1);
        float2 v2 = __half22float2(h2), v3 = __half22float2(h3);
        wsum += (p0.x + p1.x) + (p2.x + p3.x);
        ax = fmaf(p0.x, v0.x, ax); ay = fmaf(p0.x, v0.y, ay);
        ax = fmaf(p1.x, v1.x, ax); ay = fmaf(p1.x, v1.y, ay);
        ax = fmaf(p2.x, v2.x, ax); ay = fmaf(p2.x, v2.y, ay);
        ax = fmaf(p3.x, v3.x, ax); ay = fmaf(p3.x, v3.y, ay);
    }
    for (; k < end; k++) {
        float2 p = g_pair[k];
        float2 v = __half22float2(
            ((const __half2*)(g_hv + (size_t)__float_as_int(p.y) * 64))[lane]);
        wsum += p.x;
        ax = fmaf(p.x, v.x, ax);
        ay = fmaf(p.x, v.y, ay);
    }
    float inv = (end > start) ? 1.f / wsum : 0.f;
    ((float2*)(out + (size_t)n * 64))[lane] = make_float2(ax * inv, ay * inv);
}

// ---------------- launcher: dual fork ----------------------------------------
extern "C" void kernel_launch(void* const* d_in, const int* in_sizes, int n_in,
                              void* d_out, int out_size) {
    const float* node_feats = (const float*)d_in[0];
    const float* time_diff  = (const float*)d_in[1];
    const int*   src        = (const int*)d_in[2];
    const int*   dst        = (const int*)d_in[3];
    const float* W          = (const float*)d_in[4];
    const float* Wv         = (const float*)d_in[5];
    const float* omega      = (const float*)d_in[6];
    const float* Wt         = (const float*)d_in[7];
    const float* a          = (const float*)d_in[8];
    float* out = (float*)d_out;

    static cudaStream_t sB = nullptr, sC = nullptr;
    static cudaEvent_t evFork = nullptr, evSetup = nullptr, evScan = nullptr, evHv = nullptr;
    if (!sB) {
        cudaStreamCreateWithFlags(&sB, cudaStreamNonBlocking);
        cudaStreamCreateWithFlags(&sC, cudaStreamNonBlocking);
        cudaEventCreateWithFlags(&evFork,  cudaEventDisableTiming);
        cudaEventCreateWithFlags(&evSetup, cudaEventDisableTiming);
        cudaEventCreateWithFlags(&evScan,  cudaEventDisableTiming);
        cudaEventCreateWithFlags(&evHv,    cudaEventDisableTiming);
    }

    // branch B: CSR build (depends only on dst)
    cudaEventRecord(evFork, 0);
    cudaStreamWaitEvent(sB, evFork, 0);
    k_zero  <<<SCAN_BLOCKS, 1024, 0, sB>>>();
    k_count <<<(NE / 4 + 255) / 256, 256, 0, sB>>>(dst);
    k_scan1 <<<SCAN_BLOCKS, 1024, 0, sB>>>();
    k_scan23<<<SCAN_BLOCKS, 1024, 0, sB>>>();
    cudaEventRecord(evScan, sB);

    // main: weight prep
    k_setup<<<51, 256>>>(W, Wt, a, Wv, omega);
    cudaEventRecord(evSetup, 0);

    // branch C: value-projection GEMM (fma-pipe-bound; overlaps mem-bound scatter)
    cudaStreamWaitEvent(sC, evSetup, 0);
    k_hv<<<(NN + 63) / 64, 128, 0, sC>>>(node_feats);
    cudaEventRecord(evHv, sC);

    // main: per-node scalars -> scatter -> aggregate
    k_s12<<<(NN + 7) / 8, 256>>>(node_feats);
    cudaStreamWaitEvent(0, evScan, 0);
    k_scatter<<<(NE / 2 + 255) / 256, 256>>>(time_diff, src, dst, omega);
    cudaStreamWaitEvent(0, evHv, 0);
    k_agg<<<(NN + 7) / 8, 256>>>(out);
}